// round 1
// baseline (speedup 1.0000x reference)
#include <cuda_runtime.h>
#include <math.h>

// Problem constants
#define BATCH 16384
#define NCO   64
#define NFI   128
#define NSF   192   // NCO + NFI
#define HID   64

// ---------------- scratch (device globals; no allocation allowed) ----------------
__device__ float g_rgb_c[BATCH * NCO * 3];
__device__ float g_sig_c[BATCH * NCO];
__device__ float g_z    [BATCH * NSF];
__device__ float g_rgb_f[BATCH * NSF * 3];
__device__ float g_sig_f[BATCH * NSF];

__device__ __forceinline__ float sigmoidf_(float z) {
    return 1.0f / (1.0f + __expf(-z));
}

// ---------------- MLP kernel: one thread per sample ----------------
template <int NS, bool COARSE>
__global__ void __launch_bounds__(128) mlp_kernel(
    const float* __restrict__ org,  const float* __restrict__ dirv,
    const float* __restrict__ nearp,const float* __restrict__ farp,
    const float* __restrict__ w1,   const float* __restrict__ b1,
    const float* __restrict__ w2,   const float* __restrict__ b2,
    const float* __restrict__ wr,   const float* __restrict__ br,
    const float* __restrict__ wd,   const float* __restrict__ bd)
{
    __shared__ __align__(16) float sW1[3 * HID];
    __shared__ __align__(16) float sB1[HID];
    __shared__ __align__(16) float sW2[HID * HID];
    __shared__ __align__(16) float sB2[HID];
    __shared__ float sWr[HID * 3];
    __shared__ float sBr[3];
    __shared__ float sWd[HID];
    __shared__ float sBd;

    const int tid = threadIdx.x;
    for (int i = tid; i < HID * HID; i += 128) sW2[i] = w2[i];
    for (int i = tid; i < 3 * HID;  i += 128) { sW1[i] = w1[i]; sWr[i] = wr[i]; }
    if (tid < HID) { sB1[tid] = b1[tid]; sB2[tid] = b2[tid]; sWd[tid] = wd[tid]; }
    if (tid < 3)   sBr[tid] = br[tid];
    if (tid == 0)  sBd = bd[0];
    __syncthreads();

    const int s  = blockIdx.x * 128 + tid;
    const int b  = s / NS;
    const int ii = s - b * NS;

    float t;
    if (COARSE) {
        float tq = (ii == NS - 1) ? 1.0f : (float)ii * (1.0f / (float)(NS - 1));
        t = nearp[b] * (1.0f - tq) + farp[b] * tq;
    } else {
        t = g_z[s];
    }
    const float x0 = fmaf(t, dirv[3 * b + 0], org[3 * b + 0]);
    const float x1 = fmaf(t, dirv[3 * b + 1], org[3 * b + 1]);
    const float x2 = fmaf(t, dirv[3 * b + 2], org[3 * b + 2]);

    // layer 1: 3 -> 64, ReLU
    float h1[HID];
    const float4* W1a = (const float4*)sW1;
    const float4* B1a = (const float4*)sB1;
#pragma unroll
    for (int q = 0; q < 16; q++) {
        float4 wa = W1a[q], wb = W1a[16 + q], wc = W1a[32 + q], bb = B1a[q];
        h1[4*q+0] = fmaxf(fmaf(x2, wc.x, fmaf(x1, wb.x, fmaf(x0, wa.x, bb.x))), 0.0f);
        h1[4*q+1] = fmaxf(fmaf(x2, wc.y, fmaf(x1, wb.y, fmaf(x0, wa.y, bb.y))), 0.0f);
        h1[4*q+2] = fmaxf(fmaf(x2, wc.z, fmaf(x1, wb.z, fmaf(x0, wa.z, bb.z))), 0.0f);
        h1[4*q+3] = fmaxf(fmaf(x2, wc.w, fmaf(x1, wb.w, fmaf(x0, wa.w, bb.w))), 0.0f);
    }

    // layer 2: 64 -> 64, ReLU (fully unrolled so h1/acc stay in registers)
    float acc[HID];
    const float4* B2a = (const float4*)sB2;
#pragma unroll
    for (int q = 0; q < 16; q++) {
        float4 bb = B2a[q];
        acc[4*q+0] = bb.x; acc[4*q+1] = bb.y; acc[4*q+2] = bb.z; acc[4*q+3] = bb.w;
    }
#pragma unroll
    for (int k = 0; k < HID; k++) {
        const float a = h1[k];
        const float4* row = (const float4*)(sW2 + (k << 6));
#pragma unroll
        for (int q = 0; q < 16; q++) {
            float4 wv = row[q];
            acc[4*q+0] = fmaf(a, wv.x, acc[4*q+0]);
            acc[4*q+1] = fmaf(a, wv.y, acc[4*q+1]);
            acc[4*q+2] = fmaf(a, wv.z, acc[4*q+2]);
            acc[4*q+3] = fmaf(a, wv.w, acc[4*q+3]);
        }
    }

    // heads: rgb (sigmoid) + density (relu)
    float r0 = sBr[0], r1 = sBr[1], r2 = sBr[2], dns = sBd;
#pragma unroll
    for (int k = 0; k < HID; k++) {
        const float hv = fmaxf(acc[k], 0.0f);
        r0  = fmaf(hv, sWr[3 * k + 0], r0);
        r1  = fmaf(hv, sWr[3 * k + 1], r1);
        r2  = fmaf(hv, sWr[3 * k + 2], r2);
        dns = fmaf(hv, sWd[k], dns);
    }
    float* rout = (COARSE ? g_rgb_c : g_rgb_f) + (size_t)3 * s;
    rout[0] = sigmoidf_(r0);
    rout[1] = sigmoidf_(r1);
    rout[2] = sigmoidf_(r2);
    (COARSE ? g_sig_c : g_sig_f)[s] = fmaxf(dns, 0.0f);
}

// ---------------- coarse render + inverse-CDF sampling + sorted merge ----------------
__global__ void coarse_post_kernel(
    const float* __restrict__ org, const float* __restrict__ dirv,
    const float* __restrict__ nearp, const float* __restrict__ farp,
    const float* __restrict__ bkgd, float* __restrict__ out)
{
    const int b = blockIdx.x * blockDim.x + threadIdx.x;
    if (b >= BATCH) return;

    const float nb = nearp[b], fb = farp[b];
    const float n0 = nearp[0], f0 = farp[0];
    const float dxx = dirv[3*b+0], dyy = dirv[3*b+1], dzz = dirv[3*b+2];
    const float nrm = sqrtf(dxx*dxx + dyy*dyy + dzz*dzz);
    const float o0x = org[0],  o0y = org[1],  o0z = org[2];
    const float d0x = dirv[0], d0y = dirv[1], d0z = dirv[2];

    auto TV  = [&](int i) -> float {
        float tq = (i == 63) ? 1.0f : (float)i * (1.0f / 63.0f);
        return nb * (1.0f - tq) + fb * tq;
    };
    auto TV0 = [&](int i) -> float {
        float tq = (i == 63) ? 1.0f : (float)i * (1.0f / 63.0f);
        return n0 * (1.0f - tq) + f0 * tq;
    };

    // volumetric rendering (exclusive-cumsum transmittance)
    float w[NCO];
    float S = 0.f, acc = 0.f, depth = 0.f, wt0 = 0.f, c0 = 0.f, c1 = 0.f, c2 = 0.f;
    float tcur = TV(0);
    for (int i = 0; i < NCO; i++) {
        const float tnext = (i < 63) ? TV(i + 1) : tcur;
        const float td    = (i < 63) ? (tnext - tcur) : 1e10f;
        const float dd    = g_sig_c[b * NCO + i] * td * nrm;
        const float T     = __expf(-S);
        const float alpha = 1.0f - __expf(-dd);
        const float wi    = alpha * T;
        S += dd;
        w[i] = wi;
        acc += wi;
        depth = fmaf(wi, tcur, depth);
        wt0   = fmaf(wi, TV0(i), wt0);
        const float* rp = &g_rgb_c[(size_t)(b * NCO + i) * 3];
        c0 = fmaf(wi, rp[0], c0);
        c1 = fmaf(wi, rp[1], c1);
        c2 = fmaf(wi, rp[2], c2);
        tcur = tnext;
    }
    float* ob = out + (size_t)b * 16;
    ob[0] = c0 + bkgd[0] * (1.0f - acc);
    ob[1] = c1 + bkgd[1] * (1.0f - acc);
    ob[2] = c2 + bkgd[2] * (1.0f - acc);
    ob[3] = depth;
    ob[4] = acc;
    ob[5] = acc * o0x + wt0 * d0x;   // pts0 uses samples[0] (ray-0 positions)
    ob[6] = acc * o0y + wt0 * d0y;
    ob[7] = acc * o0z + wt0 * d0z;

    // piecewise-constant pdf over w[1..62]
    float ws = 0.f;
    for (int k = 1; k <= 62; k++) ws += w[k];
    const float pad = fmaxf(1e-5f - ws, 0.0f);
    const float add = pad * (1.0f / 62.0f);
    ws += pad;
    const float inv = 1.0f / ws;
    float cdf[64];
    cdf[0] = 0.0f;
    float cs = 0.f;
    for (int k = 1; k <= 61; k++) {
        cs += (w[k] + add) * inv;
        cdf[k] = fminf(cs, 1.0f);
    }
    cdf[62] = 1.0f;

    auto BIN = [&](int k) -> float { return 0.5f * (TV(k) + TV(k + 1)); };

    // inverse-CDF samples for sorted u, merged inline with sorted t_vals
    const float ueps = 1.1920929e-07f;
    const float du = (1.0f - ueps) * (1.0f / 127.0f);
    int idx = 0, ti = 0, p = 0;
    const size_t base = (size_t)b * NSF;
    for (int s = 0; s < NFI; s++) {
        const float u = (s == 127) ? (1.0f - ueps) : (float)s * du;
        while (idx < 61 && cdf[idx + 1] <= u) idx++;
        const float gg0 = cdf[idx], gg1 = cdf[idx + 1];
        float tt = (u - gg0) / (gg1 - gg0);
        if (!(tt == tt)) tt = 0.0f;          // nan -> 0; +inf clips to 1 below
        tt = fminf(fmaxf(tt, 0.0f), 1.0f);
        const float bb0 = BIN(idx);
        const float z = fmaf(tt, BIN(idx + 1) - bb0, bb0);
        while (ti < NCO && TV(ti) <= z) { g_z[base + p] = TV(ti); p++; ti++; }
        g_z[base + p] = z; p++;
    }
    while (ti < NCO) { g_z[base + p] = TV(ti); p++; ti++; }
}

// ---------------- fine render ----------------
__global__ void fine_render_kernel(
    const float* __restrict__ org, const float* __restrict__ dirv,
    const float* __restrict__ bkgd, float* __restrict__ out)
{
    const int b = blockIdx.x * blockDim.x + threadIdx.x;
    if (b >= BATCH) return;

    const float dxx = dirv[3*b+0], dyy = dirv[3*b+1], dzz = dirv[3*b+2];
    const float nrm = sqrtf(dxx*dxx + dyy*dyy + dzz*dzz);
    const float o0x = org[0],  o0y = org[1],  o0z = org[2];
    const float d0x = dirv[0], d0y = dirv[1], d0z = dirv[2];

    const float* zr = g_z + (size_t)b * NSF;
    float S = 0.f, acc = 0.f, depth = 0.f, wz0 = 0.f, c0 = 0.f, c1 = 0.f, c2 = 0.f;
    float zc = zr[0];
    for (int i = 0; i < NSF; i++) {
        const float znext = (i < NSF - 1) ? zr[i + 1] : zc;
        const float td    = (i < NSF - 1) ? (znext - zc) : 1e10f;
        const float dd    = g_sig_f[(size_t)b * NSF + i] * td * nrm;
        const float T     = __expf(-S);
        const float alpha = 1.0f - __expf(-dd);
        const float wi    = alpha * T;
        S += dd;
        acc += wi;
        depth = fmaf(wi, zc, depth);
        wz0   = fmaf(wi, g_z[i], wz0);   // samples_f[0] quirk: ray-0 z positions
        const float* rp = &g_rgb_f[((size_t)b * NSF + i) * 3];
        c0 = fmaf(wi, rp[0], c0);
        c1 = fmaf(wi, rp[1], c1);
        c2 = fmaf(wi, rp[2], c2);
        zc = znext;
    }
    float* ob = out + (size_t)b * 16;
    ob[8]  = c0 + bkgd[0] * (1.0f - acc);
    ob[9]  = c1 + bkgd[1] * (1.0f - acc);
    ob[10] = c2 + bkgd[2] * (1.0f - acc);
    ob[11] = depth;
    ob[12] = acc;
    ob[13] = acc * o0x + wz0 * d0x;
    ob[14] = acc * o0y + wz0 * d0y;
    ob[15] = acc * o0z + wz0 * d0z;
}

// ---------------- launch ----------------
extern "C" void kernel_launch(void* const* d_in, const int* in_sizes, int n_in,
                              void* d_out, int out_size)
{
    const float* org   = (const float*)d_in[0];
    const float* dirv  = (const float*)d_in[1];
    const float* nearp = (const float*)d_in[2];
    const float* farp  = (const float*)d_in[3];
    const float* bkgd  = (const float*)d_in[4];

    const float* w1c = (const float*)d_in[5];
    const float* b1c = (const float*)d_in[6];
    const float* w2c = (const float*)d_in[7];
    const float* b2c = (const float*)d_in[8];
    const float* wrc = (const float*)d_in[9];
    const float* brc = (const float*)d_in[10];
    const float* wdc = (const float*)d_in[11];
    const float* bdc = (const float*)d_in[12];

    const float* w1f = (const float*)d_in[13];
    const float* b1f = (const float*)d_in[14];
    const float* w2f = (const float*)d_in[15];
    const float* b2f = (const float*)d_in[16];
    const float* wrf = (const float*)d_in[17];
    const float* brf = (const float*)d_in[18];
    const float* wdf = (const float*)d_in[19];
    const float* bdf = (const float*)d_in[20];

    float* out = (float*)d_out;

    mlp_kernel<NCO, true><<<(BATCH * NCO) / 128, 128>>>(
        org, dirv, nearp, farp, w1c, b1c, w2c, b2c, wrc, brc, wdc, bdc);

    coarse_post_kernel<<<BATCH / 256, 256>>>(org, dirv, nearp, farp, bkgd, out);

    mlp_kernel<NSF, false><<<(BATCH * NSF) / 128, 128>>>(
        org, dirv, nearp, farp, w1f, b1f, w2f, b2f, wrf, brf, wdf, bdf);

    fine_render_kernel<<<BATCH / 256, 256>>>(org, dirv, bkgd, out);
}